// round 2
// baseline (speedup 1.0000x reference)
#include <cuda_runtime.h>
#include <math.h>

#define DM 1024
#define SEQ 2048
#define NB 2
#define NH 16
#define HD 64
#define MTOT (NB*SEQ)   // 4096

// -------- scratch (static device memory; no runtime allocation) ----------
__device__ float g_q[MTOT * DM];
__device__ float g_k[MTOT * DM];
__device__ float g_v[MTOT * DM];
__device__ float g_ao[MTOT * DM];
__device__ float g_cos[SEQ * (HD / 2)];
__device__ float g_sin[SEQ * (HD / 2)];

// -------------------- RoPE tables (double precision) ---------------------
__global__ void rope_table_kernel() {
    int p = threadIdx.x;      // 0..31 pair index
    int s = blockIdx.x;       // 0..2047 position
    double freq = pow(10000.0, -(double)(2 * p) / 64.0);
    double ang = (double)s * freq;
    g_cos[s * 32 + p] = (float)cos(ang);
    g_sin[s * 32 + p] = (float)sin(ang);
}

// ------------------- 128x128x16 SGEMM, out = X @ W^T + b -----------------
// X: (4096,1024) row-major, W: (1024,1024) row-major (n,k), out: (4096,1024)
// ROPE: apply rotary embedding in the epilogue (seq pos = row % SEQ).
template <bool ROPE>
__global__ __launch_bounds__(256) void gemm_kernel(
    const float* __restrict__ X, const float* __restrict__ W,
    const float* __restrict__ bias, float* __restrict__ out)
{
    __shared__ float As[16][132];
    __shared__ float Bs[16][132];

    const int tid = threadIdx.x;
    const int m0 = blockIdx.y * 128;
    const int n0 = blockIdx.x * 128;
    const int ri = tid >> 4;     // 0..15  (m sub-tile)
    const int cj = tid & 15;     // 0..15  (n sub-tile)

    float acc[8][8];
#pragma unroll
    for (int i = 0; i < 8; i++)
#pragma unroll
        for (int j = 0; j < 8; j++) acc[i][j] = 0.0f;

    for (int kt = 0; kt < 1024; kt += 16) {
#pragma unroll
        for (int i = 0; i < 2; i++) {
            int f = tid + i * 256;          // 0..511
            int r = f >> 2;                 // 0..127
            int kq = f & 3;                 // 0..3 (float4 group in k)
            float4 av = *(const float4*)&X[(size_t)(m0 + r) * DM + kt + kq * 4];
            As[kq * 4 + 0][r] = av.x;
            As[kq * 4 + 1][r] = av.y;
            As[kq * 4 + 2][r] = av.z;
            As[kq * 4 + 3][r] = av.w;
            float4 bv = *(const float4*)&W[(size_t)(n0 + r) * DM + kt + kq * 4];
            Bs[kq * 4 + 0][r] = bv.x;
            Bs[kq * 4 + 1][r] = bv.y;
            Bs[kq * 4 + 2][r] = bv.z;
            Bs[kq * 4 + 3][r] = bv.w;
        }
        __syncthreads();

#pragma unroll
        for (int k = 0; k < 16; k++) {
            float4 a0 = *(const float4*)&As[k][ri * 8];
            float4 a1 = *(const float4*)&As[k][ri * 8 + 4];
            float4 b0 = *(const float4*)&Bs[k][cj * 8];
            float4 b1 = *(const float4*)&Bs[k][cj * 8 + 4];
            float av[8] = {a0.x, a0.y, a0.z, a0.w, a1.x, a1.y, a1.z, a1.w};
            float bv[8] = {b0.x, b0.y, b0.z, b0.w, b1.x, b1.y, b1.z, b1.w};
#pragma unroll
            for (int i = 0; i < 8; i++)
#pragma unroll
                for (int j = 0; j < 8; j++) acc[i][j] += av[i] * bv[j];
        }
        __syncthreads();
    }

    const int nb = n0 + cj * 8;
#pragma unroll
    for (int a = 0; a < 8; a++) {
        int m = m0 + ri * 8 + a;
        int srow = m & (SEQ - 1);
        float v[8];
#pragma unroll
        for (int j = 0; j < 8; j++) v[j] = acc[a][j] + bias[nb + j];
        if (ROPE) {
            int pbase = (nb & 63) >> 1;   // pair index of first column
#pragma unroll
            for (int q = 0; q < 4; q++) {
                float c = g_cos[srow * 32 + pbase + q];
                float sn = g_sin[srow * 32 + pbase + q];
                float e = v[2 * q], o = v[2 * q + 1];
                v[2 * q]     = e * c - o * sn;
                v[2 * q + 1] = o * c + e * sn;
            }
        }
        *(float4*)&out[(size_t)m * DM + nb]     = make_float4(v[0], v[1], v[2], v[3]);
        *(float4*)&out[(size_t)m * DM + nb + 4] = make_float4(v[4], v[5], v[6], v[7]);
    }
}

// --------------------------- flash attention -----------------------------
// grid: (SEQ/64, NB*NH).  64 queries per block, 64-key tiles, full (non-causal)
// softmax.  256 threads: thread (ri,cj) owns a 4x4 tile of the 64x64 score /
// output matrices.  Shared padded to stride 65 where rows are scalar-accessed.
#define ATT_SMEM ((64 * 65 * 3 + 64 * 64) * 4)

extern __shared__ float att_sm[];

__global__ __launch_bounds__(256) void attn_kernel()
{
    float* Qs = att_sm;               // [64][65]
    float* Ks = Qs + 64 * 65;         // [64][65]
    float* Ps = Ks + 64 * 65;         // [64][65]
    float* Vs = Ps + 64 * 65;         // [64][64]

    const int tid = threadIdx.x;
    const int ri = tid >> 4;          // query group
    const int cj = tid & 15;          // key/dim group
    const int q0 = blockIdx.x * 64;
    const int bh = blockIdx.y;
    const int b = bh >> 4;
    const int h = bh & 15;
    const float scale = 0.125f;       // 1/sqrt(64)

    const size_t base = (size_t)b * SEQ * DM + (size_t)h * HD;

    // load + pre-scale Q tile
#pragma unroll
    for (int i = 0; i < 4; i++) {
        int f = tid + i * 256;
        int r = f >> 4, dq = f & 15;
        float4 qv = *(const float4*)&g_q[base + (size_t)(q0 + r) * DM + dq * 4];
        float* dst = &Qs[r * 65 + dq * 4];
        dst[0] = qv.x * scale; dst[1] = qv.y * scale;
        dst[2] = qv.z * scale; dst[3] = qv.w * scale;
    }

    float o[4][4];
    float mrow[4], lrow[4];
#pragma unroll
    for (int a = 0; a < 4; a++) {
        mrow[a] = -1e30f; lrow[a] = 0.0f;
#pragma unroll
        for (int j = 0; j < 4; j++) o[a][j] = 0.0f;
    }
    __syncthreads();

    for (int kv0 = 0; kv0 < SEQ; kv0 += 64) {
        // load K (padded scalar) and V (vector) tiles
#pragma unroll
        for (int i = 0; i < 4; i++) {
            int f = tid + i * 256;
            int r = f >> 4, dq = f & 15;
            float4 kv = *(const float4*)&g_k[base + (size_t)(kv0 + r) * DM + dq * 4];
            float* kd = &Ks[r * 65 + dq * 4];
            kd[0] = kv.x; kd[1] = kv.y; kd[2] = kv.z; kd[3] = kv.w;
            float4 vv = *(const float4*)&g_v[base + (size_t)(kv0 + r) * DM + dq * 4];
            *(float4*)&Vs[r * 64 + dq * 4] = vv;
        }
        __syncthreads();

        // scores: s[a][b] = sum_d Q[ri*4+a][d] * K[cj*4+b][d]
        float s4[4][4];
#pragma unroll
        for (int a = 0; a < 4; a++)
#pragma unroll
            for (int j = 0; j < 4; j++) s4[a][j] = 0.0f;

#pragma unroll 8
        for (int d = 0; d < 64; d++) {
            float qa[4], kb[4];
#pragma unroll
            for (int a = 0; a < 4; a++) qa[a] = Qs[(ri * 4 + a) * 65 + d];
#pragma unroll
            for (int j = 0; j < 4; j++) kb[j] = Ks[(cj * 4 + j) * 65 + d];
#pragma unroll
            for (int a = 0; a < 4; a++)
#pragma unroll
                for (int j = 0; j < 4; j++) s4[a][j] += qa[a] * kb[j];
        }

        // online softmax (row reduction across the 16 cj lanes)
#pragma unroll
        for (int a = 0; a < 4; a++) {
            float tm = fmaxf(fmaxf(s4[a][0], s4[a][1]), fmaxf(s4[a][2], s4[a][3]));
#pragma unroll
            for (int off = 8; off >= 1; off >>= 1)
                tm = fmaxf(tm, __shfl_xor_sync(0xffffffffu, tm, off));
            float nm = fmaxf(mrow[a], tm);
            float alpha = __expf(mrow[a] - nm);
            mrow[a] = nm;
            float ps = 0.0f;
#pragma unroll
            for (int j = 0; j < 4; j++) {
                float p = __expf(s4[a][j] - nm);
                ps += p;
                Ps[(ri * 4 + a) * 65 + cj * 4 + j] = p;
            }
#pragma unroll
            for (int off = 8; off >= 1; off >>= 1)
                ps += __shfl_xor_sync(0xffffffffu, ps, off);
            lrow[a] = lrow[a] * alpha + ps;
#pragma unroll
            for (int j = 0; j < 4; j++) o[a][j] *= alpha;
        }
        __syncthreads();

        // O += P @ V
#pragma unroll 8
        for (int j = 0; j < 64; j++) {
            float4 v4 = *(const float4*)&Vs[j * 64 + cj * 4];
#pragma unroll
            for (int a = 0; a < 4; a++) {
                float pv = Ps[(ri * 4 + a) * 65 + j];
                o[a][0] += pv * v4.x;
                o[a][1] += pv * v4.y;
                o[a][2] += pv * v4.z;
                o[a][3] += pv * v4.w;
            }
        }
        __syncthreads();
    }

#pragma unroll
    for (int a = 0; a < 4; a++) {
        float inv = 1.0f / lrow[a];
        float4 r = make_float4(o[a][0] * inv, o[a][1] * inv,
                               o[a][2] * inv, o[a][3] * inv);
        *(float4*)&g_ao[base + (size_t)(q0 + ri * 4 + a) * DM + cj * 4] = r;
    }
}

// ------------------------------- launch ----------------------------------
extern "C" void kernel_launch(void* const* d_in, const int* in_sizes, int n_in,
                              void* d_out, int out_size)
{
    const float* x  = (const float*)d_in[0];
    const float* wq = (const float*)d_in[1];
    const float* bq = (const float*)d_in[2];
    const float* wk = (const float*)d_in[3];
    const float* bk = (const float*)d_in[4];
    const float* wv = (const float*)d_in[5];
    const float* bv = (const float*)d_in[6];
    const float* wo = (const float*)d_in[7];
    const float* bo = (const float*)d_in[8];
    float* out = (float*)d_out;

    float *qp, *kp, *vp, *aop;
    cudaGetSymbolAddress((void**)&qp,  g_q);
    cudaGetSymbolAddress((void**)&kp,  g_k);
    cudaGetSymbolAddress((void**)&vp,  g_v);
    cudaGetSymbolAddress((void**)&aop, g_ao);

    cudaFuncSetAttribute(attn_kernel,
                         cudaFuncAttributeMaxDynamicSharedMemorySize, ATT_SMEM);

    rope_table_kernel<<<SEQ, 32>>>();

    dim3 ggrid(DM / 128, MTOT / 128);   // (8, 32)
    gemm_kernel<true ><<<ggrid, 256>>>(x, wq, bq, qp);
    gemm_kernel<true ><<<ggrid, 256>>>(x, wk, bk, kp);
    gemm_kernel<false><<<ggrid, 256>>>(x, wv, bv, vp);

    dim3 agrid(SEQ / 64, NB * NH);      // (32, 32)
    attn_kernel<<<agrid, 256, ATT_SMEM>>>();

    gemm_kernel<false><<<ggrid, 256>>>(aop, wo, bo, out);
}

// round 3
// speedup vs baseline: 2.9458x; 2.9458x over previous
#include <cuda_runtime.h>
#include <math.h>
#include <stdint.h>

#define DM 1024
#define SEQ 2048
#define NB 2
#define NH 16
#define HD 64
#define MTOT (NB*SEQ)   // 4096

// -------- scratch (static device memory; no runtime allocation) ----------
__device__ float g_q[MTOT * DM];
__device__ float g_k[MTOT * DM];
__device__ float g_v[MTOT * DM];
__device__ float g_ao[MTOT * DM];
__device__ float g_cos[SEQ * (HD / 2)];
__device__ float g_sin[SEQ * (HD / 2)];

// -------------------- helpers ---------------------
__device__ __forceinline__ uint32_t f2tf32(float x) {
    uint32_t r;
    asm("cvt.rna.tf32.f32 %0, %1;" : "=r"(r) : "f"(x));
    return r;
}

__device__ __forceinline__ void mma8(float* c, const uint32_t* a,
                                     uint32_t b0, uint32_t b1) {
    asm volatile(
        "mma.sync.aligned.m16n8k8.row.col.f32.tf32.tf32.f32 "
        "{%0,%1,%2,%3}, {%4,%5,%6,%7}, {%8,%9}, {%0,%1,%2,%3};\n"
        : "+f"(c[0]), "+f"(c[1]), "+f"(c[2]), "+f"(c[3])
        : "r"(a[0]), "r"(a[1]), "r"(a[2]), "r"(a[3]), "r"(b0), "r"(b1));
}

// -------------------- RoPE tables (double precision) ---------------------
__global__ void rope_table_kernel() {
    int p = threadIdx.x;      // 0..31 pair index
    int s = blockIdx.x;       // 0..2047 position
    double freq = pow(10000.0, -(double)(2 * p) / 64.0);
    double ang = (double)s * freq;
    g_cos[s * 32 + p] = (float)cos(ang);
    g_sin[s * 32 + p] = (float)sin(ang);
}

// ------------------- tf32 tensor-core GEMM: out = X @ W^T + b ------------
// X: (4096,1024) row-major, W: (1024(n),1024(k)) row-major, out: (4096,1024)
// Block tile 128x128, BK=32, 256 threads = 8 warps, warp tile 64x32.
// Both As and Bs stored [row][k] with stride 36 (36 mod 32 == 4 -> every
// fragment access pattern is 4*g+tg : conflict-free).
#define GSTR 36

template <bool ROPE>
__global__ __launch_bounds__(256) void gemm_tc(
    const float* __restrict__ X, const float* __restrict__ W,
    const float* __restrict__ bias, float* __restrict__ out)
{
    __shared__ uint32_t As[128 * GSTR];
    __shared__ uint32_t Bs[128 * GSTR];

    const int tid  = threadIdx.x;
    const int lane = tid & 31;
    const int wid  = tid >> 5;
    const int g    = lane >> 2;     // 0..7
    const int tg   = lane & 3;      // 0..3
    const int wm   = (wid & 1) * 64;
    const int wn   = (wid >> 1) * 32;
    const int m0   = blockIdx.y * 128;
    const int n0   = blockIdx.x * 128;

    float acc[4][4][4];
#pragma unroll
    for (int mi = 0; mi < 4; mi++)
#pragma unroll
        for (int ni = 0; ni < 4; ni++)
#pragma unroll
            for (int q = 0; q < 4; q++) acc[mi][ni][q] = 0.0f;

    float4 xa[4], wb[4];

    // prologue load (kt = 0)
#pragma unroll
    for (int i = 0; i < 4; i++) {
        int f = tid + i * 256;
        int r = f >> 3, k4 = f & 7;
        xa[i] = *(const float4*)&X[(size_t)(m0 + r) * DM + k4 * 4];
        wb[i] = *(const float4*)&W[(size_t)(n0 + r) * DM + k4 * 4];
    }

    for (int kt = 0; kt < DM; kt += 32) {
        // store staged tile to smem (with tf32 conversion)
#pragma unroll
        for (int i = 0; i < 4; i++) {
            int f = tid + i * 256;
            int r = f >> 3, k4 = f & 7;
            uint4 ua = make_uint4(f2tf32(xa[i].x), f2tf32(xa[i].y),
                                  f2tf32(xa[i].z), f2tf32(xa[i].w));
            *(uint4*)&As[r * GSTR + k4 * 4] = ua;
            uint4 ub = make_uint4(f2tf32(wb[i].x), f2tf32(wb[i].y),
                                  f2tf32(wb[i].z), f2tf32(wb[i].w));
            *(uint4*)&Bs[r * GSTR + k4 * 4] = ub;
        }
        __syncthreads();

        // prefetch next tile while computing
        if (kt + 32 < DM) {
#pragma unroll
            for (int i = 0; i < 4; i++) {
                int f = tid + i * 256;
                int r = f >> 3, k4 = f & 7;
                xa[i] = *(const float4*)&X[(size_t)(m0 + r) * DM + kt + 32 + k4 * 4];
                wb[i] = *(const float4*)&W[(size_t)(n0 + r) * DM + kt + 32 + k4 * 4];
            }
        }

#pragma unroll
        for (int ks = 0; ks < 32; ks += 8) {
            uint32_t a[4][4];
#pragma unroll
            for (int mi = 0; mi < 4; mi++) {
                int r0 = wm + mi * 16 + g;
                a[mi][0] = As[r0 * GSTR + ks + tg];
                a[mi][1] = As[(r0 + 8) * GSTR + ks + tg];
                a[mi][2] = As[r0 * GSTR + ks + tg + 4];
                a[mi][3] = As[(r0 + 8) * GSTR + ks + tg + 4];
            }
#pragma unroll
            for (int ni = 0; ni < 4; ni++) {
                int rb = wn + ni * 8 + g;
                uint32_t b0 = Bs[rb * GSTR + ks + tg];
                uint32_t b1 = Bs[rb * GSTR + ks + tg + 4];
#pragma unroll
                for (int mi = 0; mi < 4; mi++)
                    mma8(acc[mi][ni], a[mi], b0, b1);
            }
        }
        __syncthreads();
    }

    // epilogue: bias (+ RoPE) + store
#pragma unroll
    for (int mi = 0; mi < 4; mi++) {
        int row = m0 + wm + mi * 16 + g;
#pragma unroll
        for (int ni = 0; ni < 4; ni++) {
            int col = n0 + wn + ni * 8 + 2 * tg;
            float b0 = bias[col], b1 = bias[col + 1];
            float v0 = acc[mi][ni][0] + b0;
            float v1 = acc[mi][ni][1] + b1;
            float v2 = acc[mi][ni][2] + b0;
            float v3 = acc[mi][ni][3] + b1;
            if (ROPE) {
                int pr = (col & 63) >> 1;
                int s0 = row & (SEQ - 1);
                int s1 = (row + 8) & (SEQ - 1);
                float c0 = g_cos[s0 * 32 + pr], sn0 = g_sin[s0 * 32 + pr];
                float c1 = g_cos[s1 * 32 + pr], sn1 = g_sin[s1 * 32 + pr];
                float e = v0, o = v1;
                v0 = e * c0 - o * sn0;
                v1 = o * c0 + e * sn0;
                e = v2; o = v3;
                v2 = e * c1 - o * sn1;
                v3 = o * c1 + e * sn1;
            }
            *(float2*)&out[(size_t)row * DM + col]       = make_float2(v0, v1);
            *(float2*)&out[(size_t)(row + 8) * DM + col] = make_float2(v2, v3);
        }
    }
}

// --------------------------- flash attention (tf32 MMA) ------------------
// grid: (SEQ/128, NB*NH), 128 threads = 4 warps. Each warp owns 32 query
// rows x full 64 key cols (S) and 32 rows x 64 dims (PV). Online softmax in
// C-fragments, row reductions across quads via shfl. P goes through smem.
#define QSTR 68   // Qs/Ks/Ps stride (68 mod 32 == 4 -> conflict-free frags)
#define VSTR 72   // Vs stride (72 mod 32 == 8 -> conflict-free frags)

#define QS_OFF 0
#define KS_OFF (128 * QSTR)
#define VS_OFF (KS_OFF + 64 * QSTR)
#define PS_OFF (VS_OFF + 64 * VSTR)
#define ATT_WORDS (PS_OFF + 128 * QSTR)
#define ATT_SMEM (ATT_WORDS * 4)

extern __shared__ uint32_t att_sm[];

__global__ __launch_bounds__(128) void attn_tc()
{
    uint32_t* Qs = att_sm + QS_OFF;   // [128][68]
    uint32_t* Ks = att_sm + KS_OFF;   // [64][68]
    uint32_t* Vs = att_sm + VS_OFF;   // [64][72]
    uint32_t* Ps = att_sm + PS_OFF;   // [128][68]

    const int tid  = threadIdx.x;
    const int lane = tid & 31;
    const int wid  = tid >> 5;        // 0..3
    const int g    = lane >> 2;
    const int tg   = lane & 3;
    const int wm   = wid * 32;

    const int q0 = blockIdx.x * 128;
    const int bh = blockIdx.y;
    const int b  = bh >> 4;
    const int h  = bh & 15;
    const float scale = 0.125f;

    const size_t base = (size_t)b * SEQ * DM + (size_t)h * HD;

    // load + pre-scale + tf32-convert Q tile (128 x 64)
#pragma unroll
    for (int i = 0; i < 16; i++) {
        int f = tid + i * 128;
        int s = f >> 4, dq = f & 15;
        float4 qv = *(const float4*)&g_q[base + (size_t)(q0 + s) * DM + dq * 4];
        uint4 u = make_uint4(f2tf32(qv.x * scale), f2tf32(qv.y * scale),
                             f2tf32(qv.z * scale), f2tf32(qv.w * scale));
        *(uint4*)&Qs[s * QSTR + dq * 4] = u;
    }

    float o[2][8][4];
    float mrow[4], lrow[4];
#pragma unroll
    for (int i = 0; i < 4; i++) { mrow[i] = -1e30f; lrow[i] = 0.0f; }
#pragma unroll
    for (int mi = 0; mi < 2; mi++)
#pragma unroll
        for (int ni = 0; ni < 8; ni++)
#pragma unroll
            for (int q = 0; q < 4; q++) o[mi][ni][q] = 0.0f;

    for (int kv0 = 0; kv0 < SEQ; kv0 += 64) {
        // load K/V tiles (64 x 64 each)
#pragma unroll
        for (int i = 0; i < 8; i++) {
            int f = tid + i * 128;
            int s = f >> 4, dq = f & 15;
            float4 kv = *(const float4*)&g_k[base + (size_t)(kv0 + s) * DM + dq * 4];
            uint4 uk = make_uint4(f2tf32(kv.x), f2tf32(kv.y),
                                  f2tf32(kv.z), f2tf32(kv.w));
            *(uint4*)&Ks[s * QSTR + dq * 4] = uk;
            float4 vv = *(const float4*)&g_v[base + (size_t)(kv0 + s) * DM + dq * 4];
            uint4 uv = make_uint4(f2tf32(vv.x), f2tf32(vv.y),
                                  f2tf32(vv.z), f2tf32(vv.w));
            *(uint4*)&Vs[s * VSTR + dq * 4] = uv;
        }
        __syncthreads();

        // ---- S = Q @ K^T (warp: 32 rows x 64 cols) ----
        float sc[2][8][4];
#pragma unroll
        for (int mi = 0; mi < 2; mi++)
#pragma unroll
            for (int ni = 0; ni < 8; ni++)
#pragma unroll
                for (int q = 0; q < 4; q++) sc[mi][ni][q] = 0.0f;

#pragma unroll
        for (int ks = 0; ks < 64; ks += 8) {
            uint32_t a[2][4];
#pragma unroll
            for (int mi = 0; mi < 2; mi++) {
                int r0 = wm + mi * 16 + g;
                a[mi][0] = Qs[r0 * QSTR + ks + tg];
                a[mi][1] = Qs[(r0 + 8) * QSTR + ks + tg];
                a[mi][2] = Qs[r0 * QSTR + ks + tg + 4];
                a[mi][3] = Qs[(r0 + 8) * QSTR + ks + tg + 4];
            }
#pragma unroll
            for (int ni = 0; ni < 8; ni++) {
                int rb = ni * 8 + g;
                uint32_t b0 = Ks[rb * QSTR + ks + tg];
                uint32_t b1 = Ks[rb * QSTR + ks + tg + 4];
#pragma unroll
                for (int mi = 0; mi < 2; mi++)
                    mma8(sc[mi][ni], a[mi], b0, b1);
            }
        }

        // ---- online softmax (rows live in quads) ----
#pragma unroll
        for (int mi = 0; mi < 2; mi++) {
#pragma unroll
            for (int hf = 0; hf < 2; hf++) {
                int idx = mi * 2 + hf;
                float vmax = -1e30f;
#pragma unroll
                for (int ni = 0; ni < 8; ni++) {
                    vmax = fmaxf(vmax, sc[mi][ni][hf * 2]);
                    vmax = fmaxf(vmax, sc[mi][ni][hf * 2 + 1]);
                }
                vmax = fmaxf(vmax, __shfl_xor_sync(0xffffffffu, vmax, 1));
                vmax = fmaxf(vmax, __shfl_xor_sync(0xffffffffu, vmax, 2));
                float nm = fmaxf(mrow[idx], vmax);
                float alpha = __expf(mrow[idx] - nm);
                mrow[idx] = nm;
                float sum = 0.0f;
                int row = wm + mi * 16 + hf * 8 + g;
#pragma unroll
                for (int ni = 0; ni < 8; ni++) {
                    float px = __expf(sc[mi][ni][hf * 2]     - nm);
                    float py = __expf(sc[mi][ni][hf * 2 + 1] - nm);
                    sum += px + py;
                    uint2 u = make_uint2(f2tf32(px), f2tf32(py));
                    *(uint2*)&Ps[row * QSTR + ni * 8 + 2 * tg] = u;
                }
                sum += __shfl_xor_sync(0xffffffffu, sum, 1);
                sum += __shfl_xor_sync(0xffffffffu, sum, 2);
                lrow[idx] = lrow[idx] * alpha + sum;
#pragma unroll
                for (int ni = 0; ni < 8; ni++) {
                    o[mi][ni][hf * 2]     *= alpha;
                    o[mi][ni][hf * 2 + 1] *= alpha;
                }
            }
        }
        __syncwarp();   // Ps rows are warp-private; cross-lane visibility only

        // ---- O += P @ V (warp: 32 rows x 64 dims) ----
#pragma unroll
        for (int ks = 0; ks < 64; ks += 8) {
            uint32_t a[2][4];
#pragma unroll
            for (int mi = 0; mi < 2; mi++) {
                int r0 = wm + mi * 16 + g;
                a[mi][0] = Ps[r0 * QSTR + ks + tg];
                a[mi][1] = Ps[(r0 + 8) * QSTR + ks + tg];
                a[mi][2] = Ps[r0 * QSTR + ks + tg + 4];
                a[mi][3] = Ps[(r0 + 8) * QSTR + ks + tg + 4];
            }
#pragma unroll
            for (int ni = 0; ni < 8; ni++) {
                uint32_t b0 = Vs[(ks + tg) * VSTR + ni * 8 + g];
                uint32_t b1 = Vs[(ks + tg + 4) * VSTR + ni * 8 + g];
#pragma unroll
                for (int mi = 0; mi < 2; mi++)
                    mma8(o[mi][ni], a[mi], b0, b1);
            }
        }
        __syncthreads();   // before next K/V overwrite
    }

    // normalize + store
    float inv[4];
#pragma unroll
    for (int i = 0; i < 4; i++) inv[i] = 1.0f / lrow[i];
#pragma unroll
    for (int mi = 0; mi < 2; mi++) {
        int row = q0 + wm + mi * 16 + g;
#pragma unroll
        for (int ni = 0; ni < 8; ni++) {
            int col = ni * 8 + 2 * tg;
            *(float2*)&g_ao[base + (size_t)row * DM + col] =
                make_float2(o[mi][ni][0] * inv[mi * 2],
                            o[mi][ni][1] * inv[mi * 2]);
            *(float2*)&g_ao[base + (size_t)(row + 8) * DM + col] =
                make_float2(o[mi][ni][2] * inv[mi * 2 + 1],
                            o[mi][ni][3] * inv[mi * 2 + 1]);
        }
    }
}

// ------------------------------- launch ----------------------------------
extern "C" void kernel_launch(void* const* d_in, const int* in_sizes, int n_in,
                              void* d_out, int out_size)
{
    const float* x  = (const float*)d_in[0];
    const float* wq = (const float*)d_in[1];
    const float* bq = (const float*)d_in[2];
    const float* wk = (const float*)d_in[3];
    const float* bk = (const float*)d_in[4];
    const float* wv = (const float*)d_in[5];
    const float* bv = (const float*)d_in[6];
    const float* wo = (const float*)d_in[7];
    const float* bo = (const float*)d_in[8];
    float* out = (float*)d_out;

    float *qp, *kp, *vp, *aop;
    cudaGetSymbolAddress((void**)&qp,  g_q);
    cudaGetSymbolAddress((void**)&kp,  g_k);
    cudaGetSymbolAddress((void**)&vp,  g_v);
    cudaGetSymbolAddress((void**)&aop, g_ao);

    cudaFuncSetAttribute(attn_tc,
                         cudaFuncAttributeMaxDynamicSharedMemorySize, ATT_SMEM);

    rope_table_kernel<<<SEQ, 32>>>();

    dim3 ggrid(DM / 128, MTOT / 128);   // (8, 32)
    gemm_tc<true ><<<ggrid, 256>>>(x, wq, bq, qp);
    gemm_tc<true ><<<ggrid, 256>>>(x, wk, bk, kp);
    gemm_tc<false><<<ggrid, 256>>>(x, wv, bv, vp);

    dim3 agrid(SEQ / 128, NB * NH);     // (16, 32)
    attn_tc<<<agrid, 128, ATT_SMEM>>>();

    gemm_tc<false><<<ggrid, 256>>>(aop, wo, bo, out);
}